// round 1
// baseline (speedup 1.0000x reference)
#include <cuda_runtime.h>
#include <cstdint>

// Problem constants
#define BB 8192
#define NN 128
#define HH 1024
#define OO 64      // 2*A
#define AA 32
#define TT 8

#define BH ((size_t)BB * HH)   // 8,388,608
#define BO ((size_t)BB * OO)   //   524,288

// Scratch (device globals — allocation-free per harness rules)
__device__ float g_u [BH];   // state@w1 + b1 (time-invariant)
__device__ float g_v1[BH];
__device__ float g_v2[BH];
__device__ float g_s1[BH];
__device__ float g_s2[BH];
__device__ float g_v3[BO];

// ---------------------------------------------------------------------------
// zero-init of membrane potentials
// ---------------------------------------------------------------------------
__global__ void zero_kernel() {
    size_t i = (size_t)blockIdx.x * blockDim.x + threadIdx.x;
    size_t stride = (size_t)gridDim.x * blockDim.x;
    for (size_t j = i; j < BH; j += stride) { g_v1[j] = 0.0f; g_v2[j] = 0.0f; }
    for (size_t j = i; j < BO; j += stride) { g_v3[j] = 0.0f; }
}

// ---------------------------------------------------------------------------
// IF node 1 fire: h1 = v1 + u ; s1 = (h1 >= 1) ; v1 = h1*(1-s1)
// ---------------------------------------------------------------------------
__global__ void fire1_kernel() {
    size_t j = (size_t)blockIdx.x * blockDim.x + threadIdx.x;
    size_t n4 = BH / 4;
    if (j >= n4) return;
    const float4* u4 = reinterpret_cast<const float4*>(g_u);
    float4* v4 = reinterpret_cast<float4*>(g_v1);
    float4* s4 = reinterpret_cast<float4*>(g_s1);
    float4 u = u4[j];
    float4 v = v4[j];
    float4 s, vn;
    float h;
    h = v.x + u.x; s.x = (h >= 1.0f) ? 1.0f : 0.0f; vn.x = h - h * s.x;
    h = v.y + u.y; s.y = (h >= 1.0f) ? 1.0f : 0.0f; vn.y = h - h * s.y;
    h = v.z + u.z; s.z = (h >= 1.0f) ? 1.0f : 0.0f; vn.z = h - h * s.z;
    h = v.w + u.w; s.w = (h >= 1.0f) ? 1.0f : 0.0f; vn.w = h - h * s.w;
    v4[j] = vn;
    s4[j] = s;
}

// ---------------------------------------------------------------------------
// Tiled fp32 GEMM with fused epilogues.
//   MODE 0: outp = A@B + bias                       (u = state@w1 + b1)
//   MODE 1: h = vp + A@B + bias; s = h>=1;
//           vp = h*(1-s); outp = s                  (IF node 2)
//   MODE 2: x = A@B + bias; vp = 0.5*(vp + x)       (LIF output, tau=2)
// A: MxK row-major, B: KxN row-major, C: MxN row-major.
// Requires M%BM==0, N%BN==0, K%BK==0 (true for all our shapes).
// ---------------------------------------------------------------------------
template<int BM, int BN, int BK, int TM, int TN, int MODE>
__global__ __launch_bounds__((BM/TM)*(BN/TN))
void gemm_k(const float* __restrict__ A, const float* __restrict__ Bm,
            const float* __restrict__ bias,
            float* __restrict__ outp, float* __restrict__ vp,
            int M, int N, int K)
{
    __shared__ float As[BK][BM];
    __shared__ float Bs[BK][BN];

    constexpr int NT = (BM / TM) * (BN / TN);
    const int tid = threadIdx.x;
    const int tx = tid % (BN / TN);
    const int ty = tid / (BN / TN);
    const int rowBase = blockIdx.y * BM;
    const int colBase = blockIdx.x * BN;

    float acc[TM][TN];
#pragma unroll
    for (int i = 0; i < TM; i++)
#pragma unroll
        for (int j = 0; j < TN; j++) acc[i][j] = 0.0f;

    for (int k0 = 0; k0 < K; k0 += BK) {
        // Load A tile (transposed into smem)
#pragma unroll
        for (int t = tid; t < BM * BK; t += NT) {
            int r = t / BK, c = t % BK;
            As[c][r] = A[(size_t)(rowBase + r) * K + (k0 + c)];
        }
        // Load B tile
#pragma unroll
        for (int t = tid; t < BK * BN; t += NT) {
            int r = t / BN, c = t % BN;
            Bs[r][c] = Bm[(size_t)(k0 + r) * N + (colBase + c)];
        }
        __syncthreads();

#pragma unroll
        for (int kk = 0; kk < BK; kk++) {
            float ra[TM], rb[TN];
#pragma unroll
            for (int i = 0; i < TM; i++) ra[i] = As[kk][ty * TM + i];
#pragma unroll
            for (int j = 0; j < TN; j++) rb[j] = Bs[kk][tx * TN + j];
#pragma unroll
            for (int i = 0; i < TM; i++)
#pragma unroll
                for (int j = 0; j < TN; j++)
                    acc[i][j] += ra[i] * rb[j];
        }
        __syncthreads();
    }

    // Epilogue
#pragma unroll
    for (int i = 0; i < TM; i++) {
        int r = rowBase + ty * TM + i;
#pragma unroll
        for (int j = 0; j < TN; j++) {
            int c = colBase + tx * TN + j;
            size_t idx = (size_t)r * N + c;
            float y = acc[i][j] + bias[c];
            if (MODE == 0) {
                outp[idx] = y;
            } else if (MODE == 1) {
                float h = vp[idx] + y;
                float s = (h >= 1.0f) ? 1.0f : 0.0f;
                vp[idx] = h - h * s;
                outp[idx] = s;
            } else {
                vp[idx] = 0.5f * (vp[idx] + y);
            }
        }
    }
}

// ---------------------------------------------------------------------------
// Final tanh-Gaussian epilogue. One warp per batch row.
// out layout: [0, B*A) = action row-major, [B*A, B*A+B) = log_prob.
// ---------------------------------------------------------------------------
__global__ void finalize_kernel(const float* __restrict__ eps, float* __restrict__ out) {
    int warp = (blockIdx.x * blockDim.x + threadIdx.x) >> 5;
    int lane = threadIdx.x & 31;
    if (warp >= BB) return;
    const float* v3r = g_v3 + (size_t)warp * OO;
    float mu = v3r[lane];
    float ls = v3r[AA + lane];
    ls = fminf(fmaxf(ls, -20.0f), 2.0f);
    float sd = expf(ls);
    float e  = eps[(size_t)warp * AA + lane];
    float z  = mu + sd * e;
    float a  = tanhf(z);
    out[(size_t)warp * AA + lane] = a;
    // log N(z; mu, sd) = -eps^2/2 - log_std - 0.5*log(2*pi)
    float lp = -0.5f * e * e - ls - 0.91893853320467274f
               - logf(1.0f - a * a + 1e-7f);
#pragma unroll
    for (int o = 16; o > 0; o >>= 1) lp += __shfl_down_sync(0xffffffffu, lp, o);
    if (lane == 0) out[(size_t)BB * AA + warp] = lp;
}

// ---------------------------------------------------------------------------
extern "C" void kernel_launch(void* const* d_in, const int* in_sizes, int n_in,
                              void* d_out, int out_size)
{
    const float* state = (const float*)d_in[0];  // (B, N)
    const float* w1    = (const float*)d_in[1];  // (N, H)
    const float* b1    = (const float*)d_in[2];  // (H,)
    const float* w2    = (const float*)d_in[3];  // (H, H)
    const float* b2    = (const float*)d_in[4];  // (H,)
    const float* w3    = (const float*)d_in[5];  // (H, 2A)
    const float* b3    = (const float*)d_in[6];  // (2A,)
    const float* eps   = (const float*)d_in[7];  // (B, A)
    float* out = (float*)d_out;

    float* u  = nullptr; float* v1 = nullptr; float* v2 = nullptr;
    float* s1 = nullptr; float* s2 = nullptr; float* v3 = nullptr;
    cudaGetSymbolAddress((void**)&u,  g_u);
    cudaGetSymbolAddress((void**)&v1, g_v1);
    cudaGetSymbolAddress((void**)&v2, g_v2);
    cudaGetSymbolAddress((void**)&s1, g_s1);
    cudaGetSymbolAddress((void**)&s2, g_s2);
    cudaGetSymbolAddress((void**)&v3, g_v3);

    // 1) zero membrane potentials
    zero_kernel<<<1024, 256>>>();

    // 2) u = state @ w1 + b1  (time-invariant across the 8 steps)
    {
        dim3 grid(HH / 128, BB / 128);
        gemm_k<128, 128, 8, 8, 8, 0><<<grid, 256>>>(state, w1, b1, u, nullptr,
                                                    BB, HH, NN);
    }

    // 3) 8 timesteps
    for (int t = 0; t < TT; t++) {
        // IF node 1 fire
        fire1_kernel<<<(unsigned)(BH / 4 / 256), 256>>>();
        // IF node 2: h2 = v2 + s1@w2 + b2, fire, reset  (writes s2, v2)
        {
            dim3 grid(HH / 128, BB / 128);
            gemm_k<128, 128, 8, 8, 8, 1><<<grid, 256>>>(s1, w2, b2, s2, v2,
                                                        BB, HH, HH);
        }
        // LIF out: x3 = s2@w3 + b3 ; v3 = 0.5*(v3 + x3)
        {
            dim3 grid(OO / 64, BB / 128);
            gemm_k<128, 64, 8, 8, 4, 2><<<grid, 256>>>(s2, w3, b3, nullptr, v3,
                                                       BB, OO, HH);
        }
    }

    // 4) tanh-Gaussian head
    finalize_kernel<<<BB / 8, 256>>>(eps, out);
}

// round 3
// speedup vs baseline: 3.3583x; 3.3583x over previous
#include <cuda_runtime.h>
#include <cuda_bf16.h>
#include <cstdint>

// Problem constants
#define BB 8192
#define NN 128
#define HH 1024
#define OO 64      // 2*A
#define AA 32
#define TT 8

#define BH ((size_t)BB * HH)
#define BO ((size_t)BB * OO)

// ---------------------------------------------------------------------------
// Scratch (device globals — allocation-free per harness rules)
// ---------------------------------------------------------------------------
__device__ float          g_u [BH];          // state@w1 + b1 (time-invariant)
__device__ float          g_v1[BH];
__device__ float          g_v2[BH];
__device__ float          g_v3[BO];
__device__ unsigned short g_s1[BH];          // spikes, bf16 bits (0 or 0x3F80)
__device__ unsigned short g_s2[BH];
__device__ unsigned short g_w2t[1024 * 3072]; // [N=1024][K=3072] bf16 hi|mid|lo
__device__ unsigned short g_w3t[64 * 3072];   // [N=64]  [K=3072] bf16 hi|mid|lo

// ---------------------------------------------------------------------------
// PTX helpers (baseline sm_103 ISA only: cp.async, ldmatrix, mma.sync)
// ---------------------------------------------------------------------------
__device__ __forceinline__ uint32_t smem_u32(const void* p) {
    uint32_t a;
    asm("{ .reg .u64 t; cvta.to.shared.u64 t, %1; cvt.u32.u64 %0, t; }" : "=r"(a) : "l"(p));
    return a;
}
__device__ __forceinline__ void cp16(uint32_t dst, const void* src) {
    asm volatile("cp.async.cg.shared.global [%0], [%1], 16;" :: "r"(dst), "l"(src));
}
#define CP_COMMIT() asm volatile("cp.async.commit_group;" ::: "memory")
#define CP_WAIT(n)  asm volatile("cp.async.wait_group %0;" :: "n"(n) : "memory")

__device__ __forceinline__ void ldsm4(uint32_t* r, uint32_t a) {
    asm volatile("ldmatrix.sync.aligned.m8n8.x4.shared.b16 {%0,%1,%2,%3}, [%4];"
                 : "=r"(r[0]), "=r"(r[1]), "=r"(r[2]), "=r"(r[3]) : "r"(a));
}
__device__ __forceinline__ void mma16816(float* c, const uint32_t* a, const uint32_t* b) {
    asm volatile("mma.sync.aligned.m16n8k16.row.col.f32.bf16.bf16.f32 "
                 "{%0,%1,%2,%3}, {%4,%5,%6,%7}, {%8,%9}, {%0,%1,%2,%3};"
                 : "+f"(c[0]), "+f"(c[1]), "+f"(c[2]), "+f"(c[3])
                 : "r"(a[0]), "r"(a[1]), "r"(a[2]), "r"(a[3]), "r"(b[0]), "r"(b[1]));
}

// ---------------------------------------------------------------------------
// zero-init of membrane potentials
// ---------------------------------------------------------------------------
__global__ void zero_kernel() {
    size_t i = (size_t)blockIdx.x * blockDim.x + threadIdx.x;
    size_t stride = (size_t)gridDim.x * blockDim.x;
    for (size_t j = i; j < BH; j += stride) { g_v1[j] = 0.0f; g_v2[j] = 0.0f; }
    for (size_t j = i; j < BO; j += stride) g_v3[j] = 0.0f;
}

// ---------------------------------------------------------------------------
// Weight prep: [N][3072] bf16 K-major; 3-term split w = hi + mid + lo
// ---------------------------------------------------------------------------
__global__ void prep_w2t(const float* __restrict__ w2) {
    int t = blockIdx.x * blockDim.x + threadIdx.x;            // 1M threads
    if (t >= 1024 * 1024) return;
    int n = t & 1023, k = t >> 10;
    float w = w2[(size_t)k * 1024 + n];
    __nv_bfloat16 hi = __float2bfloat16(w);
    float r1 = w - __bfloat162float(hi);
    __nv_bfloat16 mid = __float2bfloat16(r1);
    __nv_bfloat16 lo  = __float2bfloat16(r1 - __bfloat162float(mid));
    size_t base = (size_t)n * 3072;
    g_w2t[base + k]        = __bfloat16_as_ushort(hi);
    g_w2t[base + 1024 + k] = __bfloat16_as_ushort(mid);
    g_w2t[base + 2048 + k] = __bfloat16_as_ushort(lo);
}
__global__ void prep_w3t(const float* __restrict__ w3) {
    int t = blockIdx.x * blockDim.x + threadIdx.x;            // 64K threads
    if (t >= 64 * 1024) return;
    int n = t & 63, k = t >> 6;
    float w = w3[(size_t)k * 64 + n];
    __nv_bfloat16 hi = __float2bfloat16(w);
    float r1 = w - __bfloat162float(hi);
    __nv_bfloat16 mid = __float2bfloat16(r1);
    __nv_bfloat16 lo  = __float2bfloat16(r1 - __bfloat162float(mid));
    size_t base = (size_t)n * 3072;
    g_w3t[base + k]        = __bfloat16_as_ushort(hi);
    g_w3t[base + 1024 + k] = __bfloat16_as_ushort(mid);
    g_w3t[base + 2048 + k] = __bfloat16_as_ushort(lo);
}

// ---------------------------------------------------------------------------
// IF node 1 fire: h1 = v1 + u ; s1 = (h1 >= 1) ; v1 = h1*(1-s1); s1 -> bf16
// ---------------------------------------------------------------------------
__global__ void fire1_kernel() {
    size_t j = (size_t)blockIdx.x * blockDim.x + threadIdx.x;
    size_t n4 = BH / 4;
    if (j >= n4) return;
    const float4* u4 = reinterpret_cast<const float4*>(g_u);
    float4* v4 = reinterpret_cast<float4*>(g_v1);
    ushort4* s4 = reinterpret_cast<ushort4*>(g_s1);
    float4 u = u4[j];
    float4 v = v4[j];
    float4 vn; ushort4 s; float h;
    h = v.x + u.x; s.x = (h >= 1.0f) ? 0x3F80 : 0; vn.x = (h >= 1.0f) ? 0.0f : h;
    h = v.y + u.y; s.y = (h >= 1.0f) ? 0x3F80 : 0; vn.y = (h >= 1.0f) ? 0.0f : h;
    h = v.z + u.z; s.z = (h >= 1.0f) ? 0x3F80 : 0; vn.z = (h >= 1.0f) ? 0.0f : h;
    h = v.w + u.w; s.w = (h >= 1.0f) ? 0x3F80 : 0; vn.w = (h >= 1.0f) ? 0.0f : h;
    v4[j] = vn;
    s4[j] = s;
}

// ---------------------------------------------------------------------------
// SIMT fp32 GEMM for g1 (u = state @ w1 + b1), K=128 only. Exact fp32 math.
// ---------------------------------------------------------------------------
template<int BM, int BN, int BK, int TM, int TN>
__global__ __launch_bounds__((BM/TM)*(BN/TN))
void gemm_g1(const float* __restrict__ A, const float* __restrict__ Bm,
             const float* __restrict__ bias, float* __restrict__ outp,
             int M, int N, int K)
{
    __shared__ float As[BK][BM];
    __shared__ float Bs[BK][BN];
    constexpr int NTH = (BM / TM) * (BN / TN);
    const int tid = threadIdx.x;
    const int tx = tid % (BN / TN);
    const int ty = tid / (BN / TN);
    const int rowBase = blockIdx.y * BM;
    const int colBase = blockIdx.x * BN;
    float acc[TM][TN];
#pragma unroll
    for (int i = 0; i < TM; i++)
#pragma unroll
        for (int j = 0; j < TN; j++) acc[i][j] = 0.0f;

    for (int k0 = 0; k0 < K; k0 += BK) {
#pragma unroll
        for (int t = tid; t < BM * BK; t += NTH) {
            int r = t / BK, c = t % BK;
            As[c][r] = A[(size_t)(rowBase + r) * K + (k0 + c)];
        }
#pragma unroll
        for (int t = tid; t < BK * BN; t += NTH) {
            int r = t / BN, c = t % BN;
            Bs[r][c] = Bm[(size_t)(k0 + r) * N + (colBase + c)];
        }
        __syncthreads();
#pragma unroll
        for (int kk = 0; kk < BK; kk++) {
            float ra[TM], rb[TN];
#pragma unroll
            for (int i = 0; i < TM; i++) ra[i] = As[kk][ty * TM + i];
#pragma unroll
            for (int j = 0; j < TN; j++) rb[j] = Bs[kk][tx * TN + j];
#pragma unroll
            for (int i = 0; i < TM; i++)
#pragma unroll
                for (int j = 0; j < TN; j++)
                    acc[i][j] += ra[i] * rb[j];
        }
        __syncthreads();
    }
#pragma unroll
    for (int i = 0; i < TM; i++) {
        int r = rowBase + ty * TM + i;
#pragma unroll
        for (int j = 0; j < TN; j++) {
            int c = colBase + tx * TN + j;
            outp[(size_t)r * N + c] = acc[i][j] + bias[c];
        }
    }
}

// ---------------------------------------------------------------------------
// mma.sync bf16 GEMM with fused spiking epilogues.
//   C[M=8192, Ntot] = A[M][1024] @ Bt[Ntot][3072]^T  (A k-index wraps mod 1024)
//   MODE 1 (IF node 2): h = vp + C + bias; s = h>=1; vp = h*(1-s); sp = s(bf16)
//   MODE 2 (LIF):       vp = 0.5*(vp + C + bias)
// Tiles: BM=128, BK=64, BN param. 8 warps (WARPS_M x WARPS_N), 3-stage cp.async.
// ---------------------------------------------------------------------------
template<int BN, int WARPS_M, int WARPS_N, int MODE>
__global__ __launch_bounds__(256, 2)
void gemm_mma(const unsigned short* __restrict__ A,
              const unsigned short* __restrict__ Bt,
              const float* __restrict__ bias,
              float* __restrict__ vp,
              unsigned short* __restrict__ sp,
              int ldc)
{
    constexpr int BM = 128;
    constexpr int BK = 64;
    constexpr int KTOT = 3072;
    constexpr int NIT = KTOT / BK;           // 48
    constexpr int STAGES = 3;
    constexpr int ATB = BM * 128;            // 16384 B per A stage (128B rows)
    constexpr int BTB = BN * 128;            // B stage bytes
    constexpr int STAGE = ATB + BTB;
    constexpr int WTM = BM / WARPS_M;        // 32 or 16
    constexpr int MT = WTM / 16;             // 2 or 1

    extern __shared__ char dsm[];
    const uint32_t sbase = smem_u32(dsm);

    const int tid = threadIdx.x;
    const int wid = tid >> 5;
    const int lane = tid & 31;
    const int wm = wid % WARPS_M;
    const int wn = wid / WARPS_M;
    const int rowBase = blockIdx.y * BM;
    const int colBase = blockIdx.x * BN;

    // ---- async tile loader ----
    auto load_tile = [&](int buf, int it) {
        const uint32_t sA = sbase + buf * STAGE;
        const uint32_t sB = sA + ATB;
        const int kb = it * BK;
        const int kA = kb & 1023;
        // A: 128 rows x 8 chunks of 16B
#pragma unroll
        for (int i = 0; i < (BM * 8) / 256; ++i) {
            int idx = i * 256 + tid;
            int r = idx >> 3, q = idx & 7;
            const void* src = A + (size_t)(rowBase + r) * 1024 + kA + q * 8;
            cp16(sA + r * 128 + ((q ^ (r & 7)) << 4), src);
        }
        // B: BN rows x 8 chunks of 16B
#pragma unroll
        for (int i = 0; i < (BN * 8) / 256; ++i) {
            int idx = i * 256 + tid;
            int r = idx >> 3, q = idx & 7;
            const void* src = Bt + (size_t)(colBase + r) * 3072 + kb + q * 8;
            cp16(sB + r * 128 + ((q ^ (r & 7)) << 4), src);
        }
    };

    float acc[MT][8][4];
#pragma unroll
    for (int mt = 0; mt < MT; ++mt)
#pragma unroll
        for (int nt = 0; nt < 8; ++nt)
#pragma unroll
            for (int x = 0; x < 4; ++x) acc[mt][nt][x] = 0.0f;

    // prefetch STAGES-1 tiles
#pragma unroll
    for (int p = 0; p < STAGES - 1; ++p) { load_tile(p, p); CP_COMMIT(); }

    // per-lane fragment address components
    const int rA0 = wm * WTM + (lane & 15);       // + mt*16
    const int qAsel = lane >> 4;                  // 0/1
    const int nB0 = wn * 64 + (lane >> 4) * 8 + (lane & 7);  // + j*8 (j step 2)
    const int qBsel = (lane >> 3) & 1;

    for (int it = 0; it < NIT; ++it) {
        CP_WAIT(STAGES - 2);
        __syncthreads();
        if (it + STAGES - 1 < NIT) load_tile((it + STAGES - 1) % STAGES, it + STAGES - 1);
        CP_COMMIT();

        const uint32_t sA = sbase + (it % STAGES) * STAGE;
        const uint32_t sB = sA + ATB;

#pragma unroll
        for (int s = 0; s < 4; ++s) {
            uint32_t a[MT][4];
#pragma unroll
            for (int mt = 0; mt < MT; ++mt) {
                int r = rA0 + mt * 16;
                int q = 2 * s + qAsel;
                ldsm4(a[mt], sA + r * 128 + ((q ^ (r & 7)) << 4));
            }
            uint32_t b[8][2];
#pragma unroll
            for (int j = 0; j < 8; j += 2) {
                int n = nB0 + j * 8;
                int q = 2 * s + qBsel;
                uint32_t t4[4];
                ldsm4(t4, sB + n * 128 + ((q ^ (n & 7)) << 4));
                b[j][0] = t4[0]; b[j][1] = t4[1];
                b[j + 1][0] = t4[2]; b[j + 1][1] = t4[3];
            }
#pragma unroll
            for (int mt = 0; mt < MT; ++mt)
#pragma unroll
                for (int nt = 0; nt < 8; ++nt)
                    mma16816(acc[mt][nt], a[mt], b[nt]);
        }
    }

    // ---- fused epilogue ----
#pragma unroll
    for (int mt = 0; mt < MT; ++mt) {
        int r0 = rowBase + wm * WTM + mt * 16 + (lane >> 2);
#pragma unroll
        for (int nt = 0; nt < 8; ++nt) {
            int c = colBase + wn * 64 + nt * 8 + (lane & 3) * 2;
            float bi0 = bias[c], bi1 = bias[c + 1];
#pragma unroll
            for (int hrow = 0; hrow < 2; ++hrow) {
                int r = r0 + hrow * 8;
                size_t idx = (size_t)r * ldc + c;
                float a0 = acc[mt][nt][hrow * 2 + 0];
                float a1 = acc[mt][nt][hrow * 2 + 1];
                float2 v = *reinterpret_cast<float2*>(vp + idx);
                if (MODE == 1) {
                    float h0 = v.x + a0 + bi0;
                    float h1 = v.y + a1 + bi1;
                    ushort2 sv;
                    sv.x = (h0 >= 1.0f) ? 0x3F80 : 0;
                    sv.y = (h1 >= 1.0f) ? 0x3F80 : 0;
                    v.x = (h0 >= 1.0f) ? 0.0f : h0;
                    v.y = (h1 >= 1.0f) ? 0.0f : h1;
                    *reinterpret_cast<float2*>(vp + idx) = v;
                    *reinterpret_cast<ushort2*>(sp + idx) = sv;
                } else {
                    v.x = 0.5f * (v.x + a0 + bi0);
                    v.y = 0.5f * (v.y + a1 + bi1);
                    *reinterpret_cast<float2*>(vp + idx) = v;
                }
            }
        }
    }
}

// ---------------------------------------------------------------------------
// Final tanh-Gaussian epilogue. One warp per batch row.
// ---------------------------------------------------------------------------
__global__ void finalize_kernel(const float* __restrict__ eps, float* __restrict__ out) {
    int warp = (blockIdx.x * blockDim.x + threadIdx.x) >> 5;
    int lane = threadIdx.x & 31;
    if (warp >= BB) return;
    const float* v3r = g_v3 + (size_t)warp * OO;
    float mu = v3r[lane];
    float ls = v3r[AA + lane];
    ls = fminf(fmaxf(ls, -20.0f), 2.0f);
    float sd = expf(ls);
    float e  = eps[(size_t)warp * AA + lane];
    float z  = mu + sd * e;
    float a  = tanhf(z);
    out[(size_t)warp * AA + lane] = a;
    float lp = -0.5f * e * e - ls - 0.91893853320467274f
               - logf(1.0f - a * a + 1e-7f);
#pragma unroll
    for (int o = 16; o > 0; o >>= 1) lp += __shfl_down_sync(0xffffffffu, lp, o);
    if (lane == 0) out[(size_t)BB * AA + warp] = lp;
}

// ---------------------------------------------------------------------------
extern "C" void kernel_launch(void* const* d_in, const int* in_sizes, int n_in,
                              void* d_out, int out_size)
{
    const float* state = (const float*)d_in[0];
    const float* w1    = (const float*)d_in[1];
    const float* b1    = (const float*)d_in[2];
    const float* w2    = (const float*)d_in[3];
    const float* b2    = (const float*)d_in[4];
    const float* w3    = (const float*)d_in[5];
    const float* b3    = (const float*)d_in[6];
    const float* eps   = (const float*)d_in[7];
    float* out = (float*)d_out;

    float* u = nullptr; float* v2 = nullptr; float* v3 = nullptr;
    unsigned short* s1 = nullptr; unsigned short* s2 = nullptr;
    unsigned short* w2t = nullptr; unsigned short* w3t = nullptr;
    cudaGetSymbolAddress((void**)&u,   g_u);
    cudaGetSymbolAddress((void**)&v2,  g_v2);
    cudaGetSymbolAddress((void**)&v3,  g_v3);
    cudaGetSymbolAddress((void**)&s1,  g_s1);
    cudaGetSymbolAddress((void**)&s2,  g_s2);
    cudaGetSymbolAddress((void**)&w2t, g_w2t);
    cudaGetSymbolAddress((void**)&w3t, g_w3t);

    const int SM2 = 3 * (128 * 128 + 128 * 128); // 98304
    const int SM3 = 3 * (128 * 128 + 64 * 128);  // 73728
    cudaFuncSetAttribute(gemm_mma<128, 4, 2, 1>, cudaFuncAttributeMaxDynamicSharedMemorySize, SM2);
    cudaFuncSetAttribute(gemm_mma<64, 8, 1, 2>,  cudaFuncAttributeMaxDynamicSharedMemorySize, SM3);

    // 1) zero membrane potentials
    zero_kernel<<<1024, 256>>>();

    // 2) weight prep (3-term bf16 split, K-major transpose)
    prep_w2t<<<(1024 * 1024) / 256, 256>>>(w2);
    prep_w3t<<<(64 * 1024) / 256, 256>>>(w3);

    // 3) u = state @ w1 + b1 (fp32 SIMT, K=128; time-invariant)
    {
        dim3 grid(HH / 128, BB / 128);
        gemm_g1<128, 128, 8, 8, 8><<<grid, 256>>>(state, w1, b1, u, BB, HH, NN);
    }

    // 4) 8 timesteps
    for (int t = 0; t < TT; t++) {
        fire1_kernel<<<(unsigned)(BH / 4 / 256), 256>>>();
        {   // IF node 2: h2 = v2 + s1@w2 + b2; fire; reset; s2 out (bf16)
            dim3 grid(HH / 128, BB / 128);
            gemm_mma<128, 4, 2, 1><<<grid, 256, SM2>>>(s1, w2t, b2, v2, s2, HH);
        }
        {   // LIF: v3 = 0.5*(v3 + s2@w3 + b3)
            dim3 grid(1, BB / 128);
            gemm_mma<64, 8, 1, 2><<<grid, 256, SM3>>>(s2, w3t, b3, v3, nullptr, OO);
        }
    }

    // 5) tanh-Gaussian head
    finalize_kernel<<<BB / 8, 256>>>(eps, out);
}

// round 4
// speedup vs baseline: 5.3511x; 1.5934x over previous
#include <cuda_runtime.h>
#include <cuda_bf16.h>
#include <cstdint>

// Problem constants
#define BB 8192
#define NN 128
#define HH 1024
#define OO 64      // 2*A
#define AA 32
#define TT 8

#define BH ((size_t)BB * HH)
#define BO ((size_t)BB * OO)

// ---------------------------------------------------------------------------
// Scratch (device globals — allocation-free per harness rules)
// ---------------------------------------------------------------------------
__device__ float          g_u    [BH];           // state@w1 + b1 (time-invariant)
__device__ unsigned short g_s1all[TT * BH];      // s1 for all 8 steps, bf16 bits
__device__ float          g_x2   [TT * BH];      // s1@w2 for all 8 steps
__device__ unsigned short g_sacc [BH];           // sum_t 2^(t-8) s2(t), bf16 (exact)
__device__ float          g_v3   [BO];
__device__ unsigned short g_w2t[1024 * 3072];    // [N=1024][K=3072] bf16 hi|mid|lo
__device__ unsigned short g_w3t[64 * 3072];      // [N=64]  [K=3072] bf16 hi|mid|lo
__device__ float          g_b3s[OO];             // b3 * 255/256

// ---------------------------------------------------------------------------
// PTX helpers (baseline sm_103 ISA: cp.async, ldmatrix, mma.sync)
// ---------------------------------------------------------------------------
__device__ __forceinline__ uint32_t smem_u32(const void* p) {
    uint32_t a;
    asm("{ .reg .u64 t; cvta.to.shared.u64 t, %1; cvt.u32.u64 %0, t; }" : "=r"(a) : "l"(p));
    return a;
}
__device__ __forceinline__ void cp16(uint32_t dst, const void* src) {
    asm volatile("cp.async.cg.shared.global [%0], [%1], 16;" :: "r"(dst), "l"(src));
}
#define CP_COMMIT() asm volatile("cp.async.commit_group;" ::: "memory")
#define CP_WAIT(n)  asm volatile("cp.async.wait_group %0;" :: "n"(n) : "memory")

__device__ __forceinline__ void ldsm4(uint32_t* r, uint32_t a) {
    asm volatile("ldmatrix.sync.aligned.m8n8.x4.shared.b16 {%0,%1,%2,%3}, [%4];"
                 : "=r"(r[0]), "=r"(r[1]), "=r"(r[2]), "=r"(r[3]) : "r"(a));
}
__device__ __forceinline__ void mma16816(float* c, const uint32_t* a, const uint32_t* b) {
    asm volatile("mma.sync.aligned.m16n8k16.row.col.f32.bf16.bf16.f32 "
                 "{%0,%1,%2,%3}, {%4,%5,%6,%7}, {%8,%9}, {%0,%1,%2,%3};"
                 : "+f"(c[0]), "+f"(c[1]), "+f"(c[2]), "+f"(c[3])
                 : "r"(a[0]), "r"(a[1]), "r"(a[2]), "r"(a[3]), "r"(b[0]), "r"(b[1]));
}

// ---------------------------------------------------------------------------
// Weight prep: [N][3072] bf16 K-major; 3-term split w = hi + mid + lo
// ---------------------------------------------------------------------------
__global__ void prep_w2t(const float* __restrict__ w2) {
    int t = blockIdx.x * blockDim.x + threadIdx.x;            // 1M threads
    if (t >= 1024 * 1024) return;
    int n = t & 1023, k = t >> 10;
    float w = w2[(size_t)k * 1024 + n];
    __nv_bfloat16 hi = __float2bfloat16(w);
    float r1 = w - __bfloat162float(hi);
    __nv_bfloat16 mid = __float2bfloat16(r1);
    __nv_bfloat16 lo  = __float2bfloat16(r1 - __bfloat162float(mid));
    size_t base = (size_t)n * 3072;
    g_w2t[base + k]        = __bfloat16_as_ushort(hi);
    g_w2t[base + 1024 + k] = __bfloat16_as_ushort(mid);
    g_w2t[base + 2048 + k] = __bfloat16_as_ushort(lo);
}
__global__ void prep_w3t(const float* __restrict__ w3, const float* __restrict__ b3) {
    int t = blockIdx.x * blockDim.x + threadIdx.x;            // 64K threads
    if (t >= 64 * 1024) return;
    int n = t & 63, k = t >> 6;
    float w = w3[(size_t)k * 64 + n];
    __nv_bfloat16 hi = __float2bfloat16(w);
    float r1 = w - __bfloat162float(hi);
    __nv_bfloat16 mid = __float2bfloat16(r1);
    __nv_bfloat16 lo  = __float2bfloat16(r1 - __bfloat162float(mid));
    size_t base = (size_t)n * 3072;
    g_w3t[base + k]        = __bfloat16_as_ushort(hi);
    g_w3t[base + 1024 + k] = __bfloat16_as_ushort(mid);
    g_w3t[base + 2048 + k] = __bfloat16_as_ushort(lo);
    if (t < OO) g_b3s[t] = b3[t] * (255.0f / 256.0f);
}

// ---------------------------------------------------------------------------
// fire1 for ALL 8 steps in one scan: v1 register-local, writes 8 s1 planes.
// ---------------------------------------------------------------------------
__global__ void fire1_all() {
    size_t i = (size_t)blockIdx.x * blockDim.x + threadIdx.x;
    if (i >= BH) return;
    float u = g_u[i];
    float v1 = 0.0f;
#pragma unroll
    for (int t = 0; t < TT; ++t) {
        float h = v1 + u;
        bool s = (h >= 1.0f);
        v1 = s ? 0.0f : h;
        g_s1all[(size_t)t * BH + i] = s ? 0x3F80 : 0;
    }
}

// ---------------------------------------------------------------------------
// fire2 for ALL 8 steps: v2 register-local; accumulates weighted spike sum
// sacc = sum_t 2^(t-8) * s2(t)  (exact in fp32 and in bf16: value = m/256).
// ---------------------------------------------------------------------------
__global__ void fire2_all(const float* __restrict__ b2) {
    size_t i = (size_t)blockIdx.x * blockDim.x + threadIdx.x;
    if (i >= BH) return;
    float b2v = b2[i & 1023];
    float v2 = 0.0f, sacc = 0.0f;
#pragma unroll
    for (int t = 0; t < TT; ++t) {
        float x = g_x2[(size_t)t * BH + i];
        float h = v2 + x;       // (v2 + M)
        h = h + b2v;            // ... + b2   (matches reference order)
        bool s = (h >= 1.0f);
        v2 = s ? 0.0f : h;
        if (s) sacc += (float)(1 << t) * (1.0f / 256.0f);
    }
    g_sacc[i] = __bfloat16_as_ushort(__float2bfloat16(sacc));  // exact
}

// ---------------------------------------------------------------------------
// SIMT fp32 GEMM for g1 (u = state @ w1 + b1). Bit-identical to round 3.
// ---------------------------------------------------------------------------
template<int BM, int BN, int BK, int TM, int TN>
__global__ __launch_bounds__((BM/TM)*(BN/TN))
void gemm_g1(const float* __restrict__ A, const float* __restrict__ Bm,
             const float* __restrict__ bias, float* __restrict__ outp,
             int M, int N, int K)
{
    __shared__ float As[BK][BM];
    __shared__ float Bs[BK][BN];
    constexpr int NTH = (BM / TM) * (BN / TN);
    const int tid = threadIdx.x;
    const int tx = tid % (BN / TN);
    const int ty = tid / (BN / TN);
    const int rowBase = blockIdx.y * BM;
    const int colBase = blockIdx.x * BN;
    float acc[TM][TN];
#pragma unroll
    for (int i = 0; i < TM; i++)
#pragma unroll
        for (int j = 0; j < TN; j++) acc[i][j] = 0.0f;

    for (int k0 = 0; k0 < K; k0 += BK) {
#pragma unroll
        for (int t = tid; t < BM * BK; t += NTH) {
            int r = t / BK, c = t % BK;
            As[c][r] = A[(size_t)(rowBase + r) * K + (k0 + c)];
        }
#pragma unroll
        for (int t = tid; t < BK * BN; t += NTH) {
            int r = t / BN, c = t % BN;
            Bs[r][c] = Bm[(size_t)(k0 + r) * N + (colBase + c)];
        }
        __syncthreads();
#pragma unroll
        for (int kk = 0; kk < BK; kk++) {
            float ra[TM], rb[TN];
#pragma unroll
            for (int i = 0; i < TM; i++) ra[i] = As[kk][ty * TM + i];
#pragma unroll
            for (int j = 0; j < TN; j++) rb[j] = Bs[kk][tx * TN + j];
#pragma unroll
            for (int i = 0; i < TM; i++)
#pragma unroll
                for (int j = 0; j < TN; j++)
                    acc[i][j] += ra[i] * rb[j];
        }
        __syncthreads();
    }
#pragma unroll
    for (int i = 0; i < TM; i++) {
        int r = rowBase + ty * TM + i;
#pragma unroll
        for (int j = 0; j < TN; j++) {
            int c = colBase + tx * TN + j;
            outp[(size_t)r * N + c] = acc[i][j] + bias[c];
        }
    }
}

// ---------------------------------------------------------------------------
// mma.sync bf16 GEMM.  C[M, Ntot] = A[M][AK] @ Bt[Ntot][KTOT]^T
// (A k-index wraps mod AK when KTOT > AK — used for the 3-term weight split).
//   MODE 0: outp = C + bias
//   MODE 4: outp = C               (raw store, no bias, no read)
// Tiles: BM=128, BK=64. 8 warps, 3-stage cp.async pipeline, XOR swizzle.
// ---------------------------------------------------------------------------
template<int KTOT, int AK, int BN, int WARPS_M, int WARPS_N, int MODE>
__global__ __launch_bounds__(256)
void gemm_mma(const unsigned short* __restrict__ A,
              const unsigned short* __restrict__ Bt,
              const float* __restrict__ bias,
              float* __restrict__ outp,
              int ldc)
{
    constexpr int BM = 128;
    constexpr int BK = 64;
    constexpr int NIT = KTOT / BK;
    constexpr int STAGES = 3;
    constexpr int ATB = BM * 128;
    constexpr int BTB = BN * 128;
    constexpr int STAGE = ATB + BTB;
    constexpr int WTM = BM / WARPS_M;
    constexpr int MT = WTM / 16;
    constexpr bool WRAP = (KTOT > AK);

    extern __shared__ char dsm[];
    const uint32_t sbase = smem_u32(dsm);

    const int tid = threadIdx.x;
    const int wid = tid >> 5;
    const int lane = tid & 31;
    const int wm = wid % WARPS_M;
    const int wn = wid / WARPS_M;
    const int rowBase = blockIdx.y * BM;
    const int colBase = blockIdx.x * BN;

    auto load_tile = [&](int buf, int it) {
        const uint32_t sA = sbase + buf * STAGE;
        const uint32_t sB = sA + ATB;
        const int kb = it * BK;
        const int kA = WRAP ? (kb & (AK - 1)) : kb;
#pragma unroll
        for (int i = 0; i < (BM * 8) / 256; ++i) {
            int idx = i * 256 + tid;
            int r = idx >> 3, q = idx & 7;
            const void* src = A + (size_t)(rowBase + r) * AK + kA + q * 8;
            cp16(sA + r * 128 + ((q ^ (r & 7)) << 4), src);
        }
#pragma unroll
        for (int i = 0; i < (BN * 8) / 256; ++i) {
            int idx = i * 256 + tid;
            int r = idx >> 3, q = idx & 7;
            const void* src = Bt + (size_t)(colBase + r) * KTOT + kb + q * 8;
            cp16(sB + r * 128 + ((q ^ (r & 7)) << 4), src);
        }
    };

    float acc[MT][8][4];
#pragma unroll
    for (int mt = 0; mt < MT; ++mt)
#pragma unroll
        for (int nt = 0; nt < 8; ++nt)
#pragma unroll
            for (int x = 0; x < 4; ++x) acc[mt][nt][x] = 0.0f;

#pragma unroll
    for (int p = 0; p < STAGES - 1; ++p) { load_tile(p, p); CP_COMMIT(); }

    const int rA0 = wm * WTM + (lane & 15);
    const int qAsel = lane >> 4;
    const int nB0 = wn * 64 + (lane >> 4) * 8 + (lane & 7);
    const int qBsel = (lane >> 3) & 1;

    for (int it = 0; it < NIT; ++it) {
        CP_WAIT(STAGES - 2);
        __syncthreads();
        if (it + STAGES - 1 < NIT) load_tile((it + STAGES - 1) % STAGES, it + STAGES - 1);
        CP_COMMIT();

        const uint32_t sA = sbase + (it % STAGES) * STAGE;
        const uint32_t sB = sA + ATB;

#pragma unroll
        for (int s = 0; s < 4; ++s) {
            uint32_t a[MT][4];
#pragma unroll
            for (int mt = 0; mt < MT; ++mt) {
                int r = rA0 + mt * 16;
                int q = 2 * s + qAsel;
                ldsm4(a[mt], sA + r * 128 + ((q ^ (r & 7)) << 4));
            }
            uint32_t b[8][2];
#pragma unroll
            for (int j = 0; j < 8; j += 2) {
                int n = nB0 + j * 8;
                int q = 2 * s + qBsel;
                uint32_t t4[4];
                ldsm4(t4, sB + n * 128 + ((q ^ (n & 7)) << 4));
                b[j][0] = t4[0]; b[j][1] = t4[1];
                b[j + 1][0] = t4[2]; b[j + 1][1] = t4[3];
            }
#pragma unroll
            for (int mt = 0; mt < MT; ++mt)
#pragma unroll
                for (int nt = 0; nt < 8; ++nt)
                    mma16816(acc[mt][nt], a[mt], b[nt]);
        }
    }

    // ---- epilogue ----
#pragma unroll
    for (int mt = 0; mt < MT; ++mt) {
        int r0 = rowBase + wm * WTM + mt * 16 + (lane >> 2);
#pragma unroll
        for (int nt = 0; nt < 8; ++nt) {
            int c = colBase + wn * 64 + nt * 8 + (lane & 3) * 2;
            float bi0 = (MODE == 0) ? bias[c] : 0.0f;
            float bi1 = (MODE == 0) ? bias[c + 1] : 0.0f;
#pragma unroll
            for (int hrow = 0; hrow < 2; ++hrow) {
                int r = r0 + hrow * 8;
                size_t idx = (size_t)r * ldc + c;
                float2 o;
                o.x = acc[mt][nt][hrow * 2 + 0] + bi0;
                o.y = acc[mt][nt][hrow * 2 + 1] + bi1;
                *reinterpret_cast<float2*>(outp + idx) = o;
            }
        }
    }
}

// ---------------------------------------------------------------------------
// Final tanh-Gaussian epilogue. One warp per batch row.
// ---------------------------------------------------------------------------
__global__ void finalize_kernel(const float* __restrict__ eps, float* __restrict__ out) {
    int warp = (blockIdx.x * blockDim.x + threadIdx.x) >> 5;
    int lane = threadIdx.x & 31;
    if (warp >= BB) return;
    const float* v3r = g_v3 + (size_t)warp * OO;
    float mu = v3r[lane];
    float ls = v3r[AA + lane];
    ls = fminf(fmaxf(ls, -20.0f), 2.0f);
    float sd = expf(ls);
    float e  = eps[(size_t)warp * AA + lane];
    float z  = mu + sd * e;
    float a  = tanhf(z);
    out[(size_t)warp * AA + lane] = a;
    float lp = -0.5f * e * e - ls - 0.91893853320467274f
               - logf(1.0f - a * a + 1e-7f);
#pragma unroll
    for (int o = 16; o > 0; o >>= 1) lp += __shfl_down_sync(0xffffffffu, lp, o);
    if (lane == 0) out[(size_t)BB * AA + warp] = lp;
}

// ---------------------------------------------------------------------------
extern "C" void kernel_launch(void* const* d_in, const int* in_sizes, int n_in,
                              void* d_out, int out_size)
{
    const float* state = (const float*)d_in[0];
    const float* w1    = (const float*)d_in[1];
    const float* b1    = (const float*)d_in[2];
    const float* w2    = (const float*)d_in[3];
    const float* b2    = (const float*)d_in[4];
    const float* w3    = (const float*)d_in[5];
    const float* b3    = (const float*)d_in[6];
    const float* eps   = (const float*)d_in[7];
    float* out = (float*)d_out;

    float* u = nullptr; float* v3 = nullptr; float* x2 = nullptr;
    unsigned short* s1all = nullptr; unsigned short* sacc = nullptr;
    unsigned short* w2t = nullptr; unsigned short* w3t = nullptr;
    float* b3s = nullptr;
    cudaGetSymbolAddress((void**)&u,     g_u);
    cudaGetSymbolAddress((void**)&v3,    g_v3);
    cudaGetSymbolAddress((void**)&x2,    g_x2);
    cudaGetSymbolAddress((void**)&s1all, g_s1all);
    cudaGetSymbolAddress((void**)&sacc,  g_sacc);
    cudaGetSymbolAddress((void**)&w2t,   g_w2t);
    cudaGetSymbolAddress((void**)&w3t,   g_w3t);
    cudaGetSymbolAddress((void**)&b3s,   g_b3s);

    const int SM2 = 3 * (128 * 128 + 128 * 128); // 98304
    const int SM3 = 3 * (128 * 128 + 64 * 128);  // 73728
    cudaFuncSetAttribute(gemm_mma<3072, 1024, 128, 4, 2, 4>,
                         cudaFuncAttributeMaxDynamicSharedMemorySize, SM2);
    cudaFuncSetAttribute(gemm_mma<3072, 1024, 64, 8, 1, 0>,
                         cudaFuncAttributeMaxDynamicSharedMemorySize, SM3);

    // 1) weight prep (3-term bf16 split, K-major transpose)
    prep_w2t<<<(1024 * 1024) / 256, 256>>>(w2);
    prep_w3t<<<(64 * 1024) / 256, 256>>>(w3, b3);

    // 2) u = state @ w1 + b1 (fp32 SIMT — bit-identical to passing round)
    {
        dim3 grid(HH / 128, BB / 128);
        gemm_g1<128, 128, 8, 8, 8><<<grid, 256>>>(state, w1, b1, u, BB, HH, NN);
    }

    // 3) all 8 fire1 steps in one scan (v1 in registers)
    fire1_all<<<(unsigned)((BH + 255) / 256), 256>>>();

    // 4) ONE big GEMM: X2[t,b,:] = s1(t) @ w2   (M = 8*8192 = 65536)
    {
        dim3 grid(HH / 128, (TT * BB) / 128);
        gemm_mma<3072, 1024, 128, 4, 2, 4><<<grid, 256, SM2>>>(s1all, w2t, nullptr, x2, HH);
    }

    // 5) all 8 fire2 steps in one scan; emits sacc = sum_t 2^(t-8) s2(t)
    fire2_all<<<(unsigned)((BH + 255) / 256), 256>>>(b2);

    // 6) ONE small GEMM: v3 = sacc @ w3 + (255/256) b3
    {
        dim3 grid(1, BB / 128);
        gemm_mma<3072, 1024, 64, 8, 1, 0><<<grid, 256, SM3>>>(sacc, w3t, b3s, v3, OO);
    }

    // 7) tanh-Gaussian head
    finalize_kernel<<<BB / 8, 256>>>(eps, out);
}